// round 1
// baseline (speedup 1.0000x reference)
#include <cuda_runtime.h>
#include <cstdint>

#define B_Q   256      // queries
#define N_MEM 50000    // memories
#define D_DIM 1024     // feature dim
#define BQ 128
#define BN 128
#define BK 16

// Per-query packed best: [ fkey(sim') : 32 | ~idx : 32 ]  (atomicMax-able)
__device__ unsigned long long g_best[B_Q];
__device__ int g_sel[B_Q];

// Monotonic float -> uint mapping (total order matching float compare)
__device__ __forceinline__ unsigned int fkey(float f) {
    unsigned int u = __float_as_uint(f);
    return (u & 0x80000000u) ? ~u : (u | 0x80000000u);
}

__global__ void init_kernel() {
    g_best[threadIdx.x] = 0ull;   // below any finite mapped key
}

// Fused GEMM + per-memory-row norm + per-query running (max, argmax).
// sim'(b,n) = dot(q_b, m_n) / ||m_n||   (dividing by ||q_b|| is monotone per row)
__global__ __launch_bounds__(256) void simmax_kernel(const float* __restrict__ Q,
                                                     const float* __restrict__ M) {
    __shared__ float As[BK][BQ];   // [k][q]  (transposed for conflict-light frag reads)
    __shared__ float Bs[BK][BN];   // [k][n]

    const int qtile = blockIdx.y * BQ;
    const int ntile = blockIdx.x * BN;
    const int tid = threadIdx.x;
    const int tx = tid & 15;       // n-direction (16 groups of 8 rows)
    const int ty = tid >> 4;       // q-direction (16 groups of 8 queries)

    float acc[8][8];
    float nrm[8];
#pragma unroll
    for (int i = 0; i < 8; i++) {
        nrm[i] = 0.0f;
#pragma unroll
        for (int j = 0; j < 8; j++) acc[i][j] = 0.0f;
    }

    for (int k0 = 0; k0 < D_DIM; k0 += BK) {
        // --- stage A (queries): 128 rows x 16 cols, float4 global, transposed STS
#pragma unroll
        for (int l = 0; l < 2; l++) {
            int idx = tid + l * 256;          // 0..511
            int row = idx >> 2;
            int c4  = (idx & 3) << 2;
            float4 v = *reinterpret_cast<const float4*>(
                &Q[(size_t)(qtile + row) * D_DIM + k0 + c4]);
            As[c4 + 0][row] = v.x;
            As[c4 + 1][row] = v.y;
            As[c4 + 2][row] = v.z;
            As[c4 + 3][row] = v.w;
        }
        // --- stage B (memories), zero-fill past N
#pragma unroll
        for (int l = 0; l < 2; l++) {
            int idx = tid + l * 256;
            int row = idx >> 2;
            int c4  = (idx & 3) << 2;
            int n = ntile + row;
            float4 v = make_float4(0.f, 0.f, 0.f, 0.f);
            if (n < N_MEM)
                v = *reinterpret_cast<const float4*>(
                    &M[(size_t)n * D_DIM + k0 + c4]);
            Bs[c4 + 0][row] = v.x;
            Bs[c4 + 1][row] = v.y;
            Bs[c4 + 2][row] = v.z;
            Bs[c4 + 3][row] = v.w;
        }
        __syncthreads();

#pragma unroll
        for (int kk = 0; kk < BK; kk++) {
            float4 a0 = *reinterpret_cast<const float4*>(&As[kk][ty * 8]);
            float4 a1 = *reinterpret_cast<const float4*>(&As[kk][ty * 8 + 4]);
            float4 b0 = *reinterpret_cast<const float4*>(&Bs[kk][tx * 8]);
            float4 b1 = *reinterpret_cast<const float4*>(&Bs[kk][tx * 8 + 4]);
            float a[8] = {a0.x, a0.y, a0.z, a0.w, a1.x, a1.y, a1.z, a1.w};
            float b[8] = {b0.x, b0.y, b0.z, b0.w, b1.x, b1.y, b1.z, b1.w};
#pragma unroll
            for (int j = 0; j < 8; j++) nrm[j] = fmaf(b[j], b[j], nrm[j]);
#pragma unroll
            for (int i = 0; i < 8; i++)
#pragma unroll
                for (int j = 0; j < 8; j++)
                    acc[i][j] = fmaf(a[i], b[j], acc[i][j]);
        }
        __syncthreads();
    }

    // Epilogue: sim' = dot / ||m||, fold to per-query (max, argmax), merge globally.
    float inv[8];
#pragma unroll
    for (int j = 0; j < 8; j++)
        inv[j] = 1.0f / sqrtf(fmaxf(nrm[j], 1e-30f));

#pragma unroll
    for (int i = 0; i < 8; i++) {
        unsigned long long pk = 0ull;
#pragma unroll
        for (int j = 0; j < 8; j++) {
            int n = ntile + tx * 8 + j;
            if (n < N_MEM) {
                float s = acc[i][j] * inv[j];
                unsigned long long key =
                    ((unsigned long long)fkey(s) << 32) |
                    (unsigned long long)(unsigned int)(~(unsigned int)n);
                if (key > pk) pk = key;
            }
        }
        // reduce across the 16 tx lanes (same half-warp, same ty)
#pragma unroll
        for (int off = 8; off > 0; off >>= 1) {
            unsigned long long o = __shfl_xor_sync(0xFFFFFFFFu, pk, off);
            if (o > pk) pk = o;
        }
        if (tx == 0)
            atomicMax(&g_best[qtile + ty * 8 + i], pk);
    }
}

// Recompute exact sim for the winner in fp32 and apply threshold.
__global__ __launch_bounds__(256) void finalize_kernel(const float* __restrict__ Q,
                                                       const float* __restrict__ M) {
    __shared__ float sdq[256], sdm[256], sdp[256];
    const int b = blockIdx.x;
    const int tid = threadIdx.x;

    unsigned long long pk = g_best[b];
    int idx = (int)(~(unsigned int)(pk & 0xFFFFFFFFull));

    const float* q = Q + (size_t)b * D_DIM;
    const float* m = M + (size_t)idx * D_DIM;
    float dq = 0.f, dm = 0.f, dp = 0.f;
    for (int k = tid * 4; k < D_DIM; k += 256 * 4) {
        float4 qa = *reinterpret_cast<const float4*>(&q[k]);
        float4 mb = *reinterpret_cast<const float4*>(&m[k]);
        dq += qa.x * qa.x + qa.y * qa.y + qa.z * qa.z + qa.w * qa.w;
        dm += mb.x * mb.x + mb.y * mb.y + mb.z * mb.z + mb.w * mb.w;
        dp += qa.x * mb.x + qa.y * mb.y + qa.z * mb.z + qa.w * mb.w;
    }
    sdq[tid] = dq; sdm[tid] = dm; sdp[tid] = dp;
    __syncthreads();
    for (int s = 128; s > 0; s >>= 1) {
        if (tid < s) {
            sdq[tid] += sdq[tid + s];
            sdm[tid] += sdm[tid + s];
            sdp[tid] += sdp[tid + s];
        }
        __syncthreads();
    }
    if (tid == 0) {
        float sim = sdp[0] / fmaxf(sqrtf(sdq[0]) * sqrtf(sdm[0]), 1e-8f);
        g_sel[b] = (sim > 0.6f) ? idx : -1;
    }
}

// out[b, :] = sel>=0 ? M[sel] @ W^T + bias : 0
__global__ __launch_bounds__(128) void decode_kernel(const float* __restrict__ M,
                                                     const float* __restrict__ W,
                                                     const float* __restrict__ bias,
                                                     float* __restrict__ out) {
    const int b = blockIdx.y;
    const int j = blockIdx.x * 128 + threadIdx.x;
    const int sel = g_sel[b];
    float r = 0.0f;
    if (sel >= 0) {
        const float* e = M + (size_t)sel * D_DIM;
        const float* w = W + (size_t)j * D_DIM;
        float s = 0.0f;
        for (int k = 0; k < D_DIM; k += 4) {
            float4 ev = *reinterpret_cast<const float4*>(&e[k]);
            float4 wv = *reinterpret_cast<const float4*>(&w[k]);
            s += ev.x * wv.x + ev.y * wv.y + ev.z * wv.z + ev.w * wv.w;
        }
        r = s + bias[j];
    }
    out[(size_t)b * D_DIM + j] = r;
}

extern "C" void kernel_launch(void* const* d_in, const int* in_sizes, int n_in,
                              void* d_out, int out_size) {
    const float* Q    = (const float*)d_in[0];   // [256, 1024]
    const float* M    = (const float*)d_in[1];   // [50000, 1024]
    const float* W    = (const float*)d_in[2];   // [1024, 1024]
    const float* bias = (const float*)d_in[3];   // [1024]
    float* out = (float*)d_out;                  // [256, 1024] fp32

    init_kernel<<<1, B_Q>>>();

    dim3 grid((N_MEM + BN - 1) / BN, B_Q / BQ);
    simmax_kernel<<<grid, 256>>>(Q, M);

    finalize_kernel<<<B_Q, 256>>>(Q, M);

    decode_kernel<<<dim3(D_DIM / 128, B_Q), 128>>>(M, W, bias, out);
}

// round 3
// speedup vs baseline: 6.0164x; 6.0164x over previous
#include <cuda_runtime.h>
#include <cuda_bf16.h>
#include <cstdint>

#define B_Q   256
#define N_MEM 50000
#define D_DIM 1024
#define NTILE 128
#define KC    64
#define NCHUNK (D_DIM / KC)                 // 16
#define NBLK  ((N_MEM + NTILE - 1) / NTILE) // 391

// SMEM layout (bytes, dynamic)
#define SM_Q     0                      // 256 rows x 128B (bf16, SW128)
#define SM_M     32768                  // 128 rows x 128B (bf16, SW128)
#define SM_NORM  49152                  // 128 floats (invn)
#define SMEM_TOTAL (SM_NORM + 512)

__device__ unsigned long long g_best[B_Q];
__device__ int g_sel[B_Q];
__device__ __nv_bfloat16 g_qb[B_Q * D_DIM];

__device__ __forceinline__ uint32_t smem_u32(const void* p) {
    uint32_t a;
    asm("{ .reg .u64 t; cvta.to.shared.u64 t, %1; cvt.u32.u64 %0, t; }" : "=r"(a) : "l"(p));
    return a;
}
__device__ __forceinline__ unsigned int fkey(float f) {
    unsigned int u = __float_as_uint(f);
    return (u & 0x80000000u) ? ~u : (u | 0x80000000u);
}
#define SW128(off) ((off) ^ (((off) >> 3) & 0x70))

#define LDSM_X4(r0, r1, r2, r3, a) \
    asm volatile("ldmatrix.sync.aligned.m8n8.x4.shared.b16 {%0,%1,%2,%3}, [%4];" \
                 : "=r"(r0), "=r"(r1), "=r"(r2), "=r"(r3) : "r"(a))
#define LDSM_X4_T(r0, r1, r2, r3, a) \
    asm volatile("ldmatrix.sync.aligned.m8n8.x4.trans.shared.b16 {%0,%1,%2,%3}, [%4];" \
                 : "=r"(r0), "=r"(r1), "=r"(r2), "=r"(r3) : "r"(a))
#define MMA_BF16(d, a, b0, b1) \
    asm volatile("mma.sync.aligned.m16n8k16.row.col.f32.bf16.bf16.f32 " \
                 "{%0,%1,%2,%3}, {%4,%5,%6,%7}, {%8,%9}, {%0,%1,%2,%3};" \
                 : "+f"((d)[0]), "+f"((d)[1]), "+f"((d)[2]), "+f"((d)[3]) \
                 : "r"((a)[0]), "r"((a)[1]), "r"((a)[2]), "r"((a)[3]), "r"(b0), "r"(b1))

// Q fp32 -> bf16 once; reset g_best.
__global__ __launch_bounds__(256) void prep_kernel(const float* __restrict__ Q) {
    int idx = blockIdx.x * 256 + threadIdx.x;
    const float4 v = reinterpret_cast<const float4*>(Q)[idx];
    __nv_bfloat162 p0 = __float22bfloat162_rn(make_float2(v.x, v.y));
    __nv_bfloat162 p1 = __float22bfloat162_rn(make_float2(v.z, v.w));
    uint2 w;
    w.x = *reinterpret_cast<uint32_t*>(&p0);
    w.y = *reinterpret_cast<uint32_t*>(&p1);
    reinterpret_cast<uint2*>(g_qb)[idx] = w;
    if (blockIdx.x == 0) g_best[threadIdx.x] = 0ull;
}

// Fused bf16 tensor-core GEMM (256q x 128n x 1024k) + row norms + argmax merge.
__global__ __launch_bounds__(512, 1) void simmax_mma(const float* __restrict__ Mptr) {
    extern __shared__ char smem[];
    const uint32_t sb = smem_u32(smem);
    const int tid = threadIdx.x;
    const int l   = tid & 31;
    const int wid = tid >> 5;
    const int wq  = wid >> 2;          // 0..3 : q block of 64
    const int wn  = wid & 3;           // 0..3 : n block of 32
    const int ntile = blockIdx.x * NTILE;

    float acc[4][4][4];
#pragma unroll
    for (int mt = 0; mt < 4; mt++)
#pragma unroll
        for (int nt = 0; nt < 4; nt++)
#pragma unroll
            for (int v = 0; v < 4; v++) acc[mt][nt][v] = 0.0f;

    // M loader mapping: row = tid>>2 (0..127), quarter = tid&3 (16 floats each)
    const int mrow = tid >> 2;
    const int mq4  = tid & 3;
    const int mn   = ntile + mrow;
    const bool mvalid = (mn < N_MEM);
    const float* msrc = Mptr + (size_t)mn * D_DIM + mq4 * 16;
    float sumsq = 0.0f;
    float4 f[4];

    // Q loader mapping: row = tid>>1 (0..255), half = tid&1 (64B each)
    const int qrow = tid >> 1;
    const int qh   = tid & 1;
    const __nv_bfloat16* qsrc = g_qb + (size_t)qrow * D_DIM + qh * 32;

    // ---- prologue: chunk 0
    {
#pragma unroll
        for (int i = 0; i < 4; i++)
            f[i] = mvalid ? *reinterpret_cast<const float4*>(msrc + i * 4)
                          : make_float4(0.f, 0.f, 0.f, 0.f);
#pragma unroll
        for (int i = 0; i < 4; i++) {
            uint4 v = *reinterpret_cast<const uint4*>(qsrc + i * 8);
            uint32_t off = (uint32_t)(qrow * 128 + qh * 64 + i * 16);
            *reinterpret_cast<uint4*>(smem + SM_Q + SW128(off)) = v;
        }
    }

    for (int c = 0; c < NCHUNK; c++) {
        // store current M regs (convert + fused sumsq), done for chunk c
        {
            uint32_t w[8];
#pragma unroll
            for (int i = 0; i < 4; i++) {
                sumsq += f[i].x * f[i].x + f[i].y * f[i].y + f[i].z * f[i].z + f[i].w * f[i].w;
                __nv_bfloat162 p0 = __float22bfloat162_rn(make_float2(f[i].x, f[i].y));
                __nv_bfloat162 p1 = __float22bfloat162_rn(make_float2(f[i].z, f[i].w));
                w[i * 2]     = *reinterpret_cast<uint32_t*>(&p0);
                w[i * 2 + 1] = *reinterpret_cast<uint32_t*>(&p1);
            }
            uint32_t off = (uint32_t)(mrow * 128 + mq4 * 32);
            *reinterpret_cast<uint4*>(smem + SM_M + SW128(off))      = *reinterpret_cast<uint4*>(&w[0]);
            *reinterpret_cast<uint4*>(smem + SM_M + SW128(off + 16)) = *reinterpret_cast<uint4*>(&w[4]);
        }
        __syncthreads();   // smem chunk c ready

        // prefetch M chunk c+1 into regs (DRAM latency hidden by compute)
        if (c + 1 < NCHUNK) {
#pragma unroll
            for (int i = 0; i < 4; i++)
                f[i] = mvalid ? *reinterpret_cast<const float4*>(msrc + (c + 1) * KC + i * 4)
                              : make_float4(0.f, 0.f, 0.f, 0.f);
        }

        // ---- compute chunk c
        const int arow = wq * 64 + (l & 15);
        const int ahi  = (l >> 4) * 16;
        const int brow = wn * 32 + (l & 15);
#pragma unroll
        for (int ks = 0; ks < 4; ks++) {
            uint32_t a[4][4];
#pragma unroll
            for (int mt = 0; mt < 4; mt++) {
                uint32_t off = (uint32_t)((arow + mt * 16) * 128 + ks * 32 + ahi);
                LDSM_X4(a[mt][0], a[mt][1], a[mt][2], a[mt][3], sb + SM_Q + SW128(off));
            }
            uint32_t b[2][4];
#pragma unroll
            for (int p = 0; p < 2; p++) {
                uint32_t off = (uint32_t)((brow + p * 16) * 128 + ks * 32 + ahi);
                LDSM_X4_T(b[p][0], b[p][1], b[p][2], b[p][3], sb + SM_M + SW128(off));
            }
#pragma unroll
            for (int mt = 0; mt < 4; mt++)
#pragma unroll
                for (int nt = 0; nt < 4; nt++)
                    MMA_BF16(acc[mt][nt], a[mt], b[nt >> 1][nt & 1], b[nt >> 1][(nt & 1) + 2]);
        }
        __syncthreads();   // all reads done; safe to overwrite smem
    }

    // ---- row norms -> invn (quad reduce; writer = lane with mq4==0)
    sumsq += __shfl_xor_sync(0xFFFFFFFFu, sumsq, 1);
    sumsq += __shfl_xor_sync(0xFFFFFFFFu, sumsq, 2);
    float* invn = reinterpret_cast<float*>(smem + SM_NORM);
    if (mq4 == 0) invn[mrow] = rsqrtf(fmaxf(sumsq, 1e-30f));
    __syncthreads();

    // ---- epilogue: per-q-row argmax over this CTA's 128 n
#pragma unroll
    for (int mt = 0; mt < 4; mt++) {
#pragma unroll
        for (int sub = 0; sub < 2; sub++) {
            unsigned long long best = 0ull;
#pragma unroll
            for (int nt = 0; nt < 4; nt++) {
#pragma unroll
                for (int cc = 0; cc < 2; cc++) {
                    int nl = wn * 32 + nt * 8 + 2 * (l & 3) + cc;
                    int n = ntile + nl;
                    if (n < N_MEM) {
                        float s = acc[mt][nt][sub * 2 + cc] * invn[nl];
                        unsigned long long key =
                            ((unsigned long long)fkey(s) << 32) |
                            (unsigned long long)(unsigned int)(~(unsigned int)n);
                        if (key > best) best = key;
                    }
                }
            }
            unsigned long long o;
            o = __shfl_xor_sync(0xFFFFFFFFu, best, 1); if (o > best) best = o;
            o = __shfl_xor_sync(0xFFFFFFFFu, best, 2); if (o > best) best = o;
            if ((l & 3) == 0) {
                int q = wq * 64 + mt * 16 + (l >> 2) + sub * 8;
                atomicMax(&g_best[q], best);
            }
        }
    }
}

// Exact fp32 recompute of the winner's cosine sim + threshold.
__global__ __launch_bounds__(256) void finalize_kernel(const float* __restrict__ Q,
                                                       const float* __restrict__ M) {
    __shared__ float sdq[256], sdm[256], sdp[256];
    const int b = blockIdx.x;
    const int tid = threadIdx.x;

    unsigned long long pk = g_best[b];
    int idx = (int)(~(unsigned int)(pk & 0xFFFFFFFFull));

    const float* q = Q + (size_t)b * D_DIM;
    const float* m = M + (size_t)idx * D_DIM;
    float dq = 0.f, dm = 0.f, dp = 0.f;
    for (int k = tid * 4; k < D_DIM; k += 256 * 4) {
        float4 qa = *reinterpret_cast<const float4*>(&q[k]);
        float4 mb = *reinterpret_cast<const float4*>(&m[k]);
        dq += qa.x * qa.x + qa.y * qa.y + qa.z * qa.z + qa.w * qa.w;
        dm += mb.x * mb.x + mb.y * mb.y + mb.z * mb.z + mb.w * mb.w;
        dp += qa.x * mb.x + qa.y * mb.y + qa.z * mb.z + qa.w * mb.w;
    }
    sdq[tid] = dq; sdm[tid] = dm; sdp[tid] = dp;
    __syncthreads();
    for (int s = 128; s > 0; s >>= 1) {
        if (tid < s) {
            sdq[tid] += sdq[tid + s];
            sdm[tid] += sdm[tid + s];
            sdp[tid] += sdp[tid + s];
        }
        __syncthreads();
    }
    if (tid == 0) {
        float sim = sdp[0] / fmaxf(sqrtf(sdq[0]) * sqrtf(sdm[0]), 1e-8f);
        g_sel[b] = (sim > 0.6f) ? idx : -1;
    }
}

__global__ __launch_bounds__(128) void decode_kernel(const float* __restrict__ M,
                                                     const float* __restrict__ W,
                                                     const float* __restrict__ bias,
                                                     float* __restrict__ out) {
    const int b = blockIdx.y;
    const int j = blockIdx.x * 128 + threadIdx.x;
    const int sel = g_sel[b];
    float r = 0.0f;
    if (sel >= 0) {
        const float* e = M + (size_t)sel * D_DIM;
        const float* w = W + (size_t)j * D_DIM;
        float s = 0.0f;
        for (int k = 0; k < D_DIM; k += 4) {
            float4 ev = *reinterpret_cast<const float4*>(&e[k]);
            float4 wv = *reinterpret_cast<const float4*>(&w[k]);
            s += ev.x * wv.x + ev.y * wv.y + ev.z * wv.z + ev.w * wv.w;
        }
        r = s + bias[j];
    }
    out[(size_t)b * D_DIM + j] = r;
}

extern "C" void kernel_launch(void* const* d_in, const int* in_sizes, int n_in,
                              void* d_out, int out_size) {
    const float* Q    = (const float*)d_in[0];
    const float* M    = (const float*)d_in[1];
    const float* W    = (const float*)d_in[2];
    const float* bias = (const float*)d_in[3];
    float* out = (float*)d_out;

    cudaFuncSetAttribute(simmax_mma, cudaFuncAttributeMaxDynamicSharedMemorySize, SMEM_TOTAL);

    prep_kernel<<<B_Q * D_DIM / 4 / 256, 256>>>(Q);
    simmax_mma<<<NBLK, 512, SMEM_TOTAL>>>(M);
    finalize_kernel<<<B_Q, 256>>>(Q, M);
    decode_kernel<<<dim3(D_DIM / 128, B_Q), 128>>>(M, W, bias, out);
}